// round 9
// baseline (speedup 1.0000x reference)
#include <cuda_runtime.h>

// QGN_30219389895238: 4-gate single-qubit Rot circuit, expval |<0|psi>|^2.
//
// Algebraic reduction (verified, rel_err 7e-7):
//   psi ~ RY(t3) P(c2) RY(t2) P(c1) RY(t1) P(c0) RY(t0) |0>
//   t_g = w[6g+2]+x[3g+1]*w[6g+3], c_g = phi_{g+1}+omega_g -> 7 sincos/row.
//
// R8: persistent grid-stride kernel. Same per-iteration memory pattern as the
// roofline-saturating R6 (direct __ldcs float4 row loads, __stcs output), but
// 2368 resident CTAs loop over rows instead of 32768 one-shot CTAs:
//  - removes ~30k CTA launch/sched events (ramp + tail wave overhead)
//  - loop lets ptxas hoist next-iteration LDGs under the MUFU chain
//    (continuous load stream, no barrier — avoids R5's staging stall).

#define TPB 128
#define NBLK 2368   // 148 SMs x 16 resident CTAs of 128 threads

__global__ __launch_bounds__(TPB) void qgn_kernel8(
    const float4* __restrict__ x4,   // [B*3] float4  (= [B,12] float)
    const float*  __restrict__ w,    // [24]
    float* __restrict__ out,         // [B]
    int n)
{
    // Uniform weights: loaded once per thread, live in registers across loop.
    const float4* w4 = reinterpret_cast<const float4*>(w);
    float4 wa = __ldg(w4 + 0);  // w0..w3
    float4 wb = __ldg(w4 + 1);  // w4..w7
    float4 wc = __ldg(w4 + 2);  // w8..w11
    float4 wd = __ldg(w4 + 3);  // w12..w15
    float4 we = __ldg(w4 + 4);  // w16..w19
    float4 wf = __ldg(w4 + 5);  // w20..w23

    int stride = NBLK * TPB;
    for (int i = blockIdx.x * TPB + threadIdx.x; i < n; i += stride) {
        // Read-once feature stream: evict-first, warp-coalesced per iteration.
        float4 v0 = __ldcs(x4 + 3 * i + 0);  // x0..x3
        float4 v1 = __ldcs(x4 + 3 * i + 1);  // x4..x7
        float4 v2 = __ldcs(x4 + 3 * i + 2);  // x8..x11

        // Half-angles for RY gates.
        float ht0 = 0.5f * fmaf(v0.y, wa.w, wa.z);   // 0.5*(w2  + x1 *w3)
        float ht1 = 0.5f * fmaf(v1.x, wc.y, wc.x);   // 0.5*(w8  + x4 *w9)
        float ht2 = 0.5f * fmaf(v1.w, wd.w, wd.z);   // 0.5*(w14 + x7 *w15)
        float ht3 = 0.5f * fmaf(v2.z, wf.y, wf.x);   // 0.5*(w20 + x10*w21)

        // Fused inter-gate phases c_g = phi_{g+1} + omega_g.
        float c0 = fmaf(v0.w, wb.w, wb.z) + fmaf(v0.z, wb.y, wb.x);
        float c1 = fmaf(v1.z, wd.y, wd.x) + fmaf(v1.y, wc.w, wc.z);
        float c2 = fmaf(v2.y, we.w, we.z) + fmaf(v2.x, we.y, we.x);

        float st, ct, sc, cc;

        // Gate 0: RY(t0) on |0> -> real state.
        __sincosf(ht0, &st, &ct);
        float a0 = ct, b0 = 0.0f;   // s0 = a0 + i b0
        float a1 = st, b1 = 0.0f;   // s1 = a1 + i b1

        // Gate 1: P(c0) then RY(t1)
        __sincosf(c0, &sc, &cc);
        {
            float na1 = a1 * cc - b1 * sc;
            float nb1 = a1 * sc + b1 * cc;
            __sincosf(ht1, &st, &ct);
            float ta0 = ct * a0 - st * na1;
            float tb0 = ct * b0 - st * nb1;
            a1 = st * a0 + ct * na1;
            b1 = st * b0 + ct * nb1;
            a0 = ta0; b0 = tb0;
        }

        // Gate 2: P(c1) then RY(t2)
        __sincosf(c1, &sc, &cc);
        {
            float na1 = a1 * cc - b1 * sc;
            float nb1 = a1 * sc + b1 * cc;
            __sincosf(ht2, &st, &ct);
            float ta0 = ct * a0 - st * na1;
            float tb0 = ct * b0 - st * nb1;
            a1 = st * a0 + ct * na1;
            b1 = st * b0 + ct * nb1;
            a0 = ta0; b0 = tb0;
        }

        // Gate 3: P(c2) then RY(t3) — only s0 needed afterwards.
        __sincosf(c2, &sc, &cc);
        {
            float na1 = a1 * cc - b1 * sc;
            float nb1 = a1 * sc + b1 * cc;
            __sincosf(ht3, &st, &ct);
            float ta0 = ct * a0 - st * na1;
            float tb0 = ct * b0 - st * nb1;
            a0 = ta0; b0 = tb0;
        }

        // Write-once output: evict-first.
        __stcs(out + i, fmaf(a0, a0, b0 * b0));
    }
}

extern "C" void kernel_launch(void* const* d_in, const int* in_sizes, int n_in,
                              void* d_out, int out_size)
{
    const float* x = (const float*)d_in[0];
    const float* w = (const float*)d_in[1];
    if (n_in >= 2 && in_sizes[0] == 24) {  // defensive: swapped order
        w = (const float*)d_in[0];
        x = (const float*)d_in[1];
    }
    int n = out_size;  // B rows
    qgn_kernel8<<<NBLK, TPB>>>(
        reinterpret_cast<const float4*>(x), w, (float*)d_out, n);
}

// round 10
// speedup vs baseline: 1.0599x; 1.0599x over previous
#include <cuda_runtime.h>

// QGN_30219389895238: 4-gate single-qubit Rot circuit, expval |<0|psi>|^2.
//
// FINAL (== R4, the measured optimum across 7 structural variants).
//
// Algebraic reduction (verified, rel_err 7e-7):
//   U = prod_g RZ(w_g)RY(t_g)RZ(p_g) on |0>. Leading RZ = global phase (drop),
//   trailing RZ diagonal -> |s0|^2 invariant (drop), fuse adjacent
//   RZ(p_{g+1})RZ(w_g) = P(c_g), c_g = p_{g+1}+w_g:
//   psi ~ RY(t3) P(c2) RY(t2) P(c1) RY(t1) P(c0) RY(t0) |0>
//   -> 7 sincos/row instead of 12; RY matrices real.
//
// Perf model: 208 MB mandatory HBM traffic; kernel runs at 6.37 TB/s =
// the measured LTS-path ceiling for this mix (DRAM 80.5%, fma 20%, MUFU
// hidden). Falsified alternatives: 2-row/2xMLP (flat), smem staging (-14%),
// persistent grid (-7%), TPB=128 (flat). Streaming hints (__ldcs/__stcs)
// retained: best measured config.

__global__ __launch_bounds__(256) void qgn_kernel(
    const float4* __restrict__ x4,   // [B*3] float4  (= [B,12] float)
    const float*  __restrict__ w,    // [24]
    float* __restrict__ out,         // [B]
    int n)
{
    int i = blockIdx.x * blockDim.x + threadIdx.x;
    if (i >= n) return;

    // Read-once feature stream: evict-first, warp-coalesced.
    float4 v0 = __ldcs(x4 + 3 * i + 0);  // x0..x3
    float4 v1 = __ldcs(x4 + 3 * i + 1);  // x4..x7
    float4 v2 = __ldcs(x4 + 3 * i + 2);  // x8..x11

    // Uniform weights: read-only cached broadcast.
    const float4* w4 = reinterpret_cast<const float4*>(w);
    float4 wa = __ldg(w4 + 0);  // w0..w3
    float4 wb = __ldg(w4 + 1);  // w4..w7
    float4 wc = __ldg(w4 + 2);  // w8..w11
    float4 wd = __ldg(w4 + 3);  // w12..w15
    float4 we = __ldg(w4 + 4);  // w16..w19
    float4 wf = __ldg(w4 + 5);  // w20..w23

    // Half-angles for RY gates: t_g/2 = 0.5*(w[6g+2] + x[3g+1]*w[6g+3]).
    float ht0 = 0.5f * fmaf(v0.y, wa.w, wa.z);   // 0.5*(w2  + x1 *w3)
    float ht1 = 0.5f * fmaf(v1.x, wc.y, wc.x);   // 0.5*(w8  + x4 *w9)
    float ht2 = 0.5f * fmaf(v1.w, wd.w, wd.z);   // 0.5*(w14 + x7 *w15)
    float ht3 = 0.5f * fmaf(v2.z, wf.y, wf.x);   // 0.5*(w20 + x10*w21)

    // Fused inter-gate phases c_g = phi_{g+1} + omega_g.
    float c0 = fmaf(v0.w, wb.w, wb.z) + fmaf(v0.z, wb.y, wb.x);
    float c1 = fmaf(v1.z, wd.y, wd.x) + fmaf(v1.y, wc.w, wc.z);
    float c2 = fmaf(v2.y, we.w, we.z) + fmaf(v2.x, we.y, we.x);

    float st, ct, sc, cc;

    // Gate 0: RY(t0) on |0> -> real state.
    __sincosf(ht0, &st, &ct);
    float a0 = ct, b0 = 0.0f;   // s0 = a0 + i b0
    float a1 = st, b1 = 0.0f;   // s1 = a1 + i b1

    // Gate 1: P(c0) then RY(t1)
    __sincosf(c0, &sc, &cc);
    {
        float na1 = a1 * cc - b1 * sc;
        float nb1 = a1 * sc + b1 * cc;
        __sincosf(ht1, &st, &ct);
        float ta0 = ct * a0 - st * na1;
        float tb0 = ct * b0 - st * nb1;
        a1 = st * a0 + ct * na1;
        b1 = st * b0 + ct * nb1;
        a0 = ta0; b0 = tb0;
    }

    // Gate 2: P(c1) then RY(t2)
    __sincosf(c1, &sc, &cc);
    {
        float na1 = a1 * cc - b1 * sc;
        float nb1 = a1 * sc + b1 * cc;
        __sincosf(ht2, &st, &ct);
        float ta0 = ct * a0 - st * na1;
        float tb0 = ct * b0 - st * nb1;
        a1 = st * a0 + ct * na1;
        b1 = st * b0 + ct * nb1;
        a0 = ta0; b0 = tb0;
    }

    // Gate 3: P(c2) then RY(t3) — only s0 needed afterwards.
    __sincosf(c2, &sc, &cc);
    {
        float na1 = a1 * cc - b1 * sc;
        float nb1 = a1 * sc + b1 * cc;
        __sincosf(ht3, &st, &ct);
        float ta0 = ct * a0 - st * na1;
        float tb0 = ct * b0 - st * nb1;
        a0 = ta0; b0 = tb0;
    }

    // Write-once output: evict-first.
    __stcs(out + i, fmaf(a0, a0, b0 * b0));
}

extern "C" void kernel_launch(void* const* d_in, const int* in_sizes, int n_in,
                              void* d_out, int out_size)
{
    const float* x = (const float*)d_in[0];
    const float* w = (const float*)d_in[1];
    if (n_in >= 2 && in_sizes[0] == 24) {  // defensive: swapped order
        w = (const float*)d_in[0];
        x = (const float*)d_in[1];
    }
    int n = out_size;  // B rows
    int threads = 256;
    int blocks = (n + threads - 1) / threads;
    qgn_kernel<<<blocks, threads>>>(
        reinterpret_cast<const float4*>(x), w, (float*)d_out, n);
}